// round 8
// baseline (speedup 1.0000x reference)
#include <cuda_runtime.h>
#include <cuda_bf16.h>
#include <math.h>

// S4D kernel init:  out[h,l] = 2 * Re( sum_n Ccf[h,n] * exp(dtA[h,n] * l) )
// l = j*128 + i ;  out[h,j,i] = sum_n Px[n,j]*Qr[n,i] - Py[n,j]*Qi[n,i]
//
// Round-8 = Round-7 with the inner accumulation split into two independent
// half-sweeps (all px*qr updates, then all pny*qi updates). Same-accumulator
// RAW distance goes 1 -> 16 (>= FFMA lat 4), removing the ~4-cycle stall on
// every second fma2 and letting the LDS prefetch overlap fma issue.

#define N2 32
#define NP 16          // n-rows per Q pass
#define TT 128
#define TTP 129        // padded sQ row (float2 units)
#define NTHREADS 128
#define NJ 32
#define NJP 16         // j-pairs
#define NPOW 12        // w^(2^k), k = 0..11

typedef unsigned long long u64;

__device__ __forceinline__ u64 pack2(float x, float y) {
    u64 r; asm("mov.b64 %0, {%1, %2};" : "=l"(r) : "f"(x), "f"(y)); return r;
}
__device__ __forceinline__ u64 fma2(u64 a, u64 b, u64 c) {
    u64 d; asm("fma.rn.f32x2 %0, %1, %2, %3;" : "=l"(d) : "l"(a), "l"(b), "l"(c)); return d;
}
__device__ __forceinline__ float2 unpack2(u64 v) {
    float2 f; asm("mov.b64 {%0, %1}, %2;" : "=f"(f.x), "=f"(f.y) : "l"(v)); return f;
}
__device__ __forceinline__ float2 cmul(float2 a, float2 b) {
    return make_float2(a.x * b.x - a.y * b.y, a.x * b.y + a.y * b.x);
}

__global__ __launch_bounds__(NTHREADS, 5)
void s4d_vandermonde_kernel(
    const float* __restrict__ log_dt,
    const float* __restrict__ C,          // (H, N2, 2)
    const float* __restrict__ log_A_real, // (H, N2)
    const float* __restrict__ A_imag,     // (H, N2)
    float* __restrict__ out,              // (H, L)
    int L)
{
    __shared__ float2 sQ[NP][TTP];      // 16.1 KB, padded, reused across passes
    __shared__ float4 sPc[N2][NJP];     //  8 KB : (px0, px1, -py0, -py1)
    __shared__ float2 sPow[N2][NPOW];   //  3 KB : w^(2^k)
    __shared__ float2 sCcf[N2];

    const int h    = blockIdx.x;
    const int tid  = threadIdx.x;
    const int lane = tid & 31;
    const int jt   = tid >> 5;          // warp id = j-tile (8 j = 4 pairs)

    // ---------- Phase 0: coefficients + power table ----------
    if (tid < N2) {
        const int n = tid;
        const int g = h * N2 + n;
        float dt  = expf(log_dt[h]);
        float ar0 = -expf(log_A_real[g]);   // Re(A)
        float ai0 = A_imag[g];              // Im(A)
        float ar  = ar0 * dt;               // Re(dtA)
        float ai  = ai0 * dt;               // Im(dtA)
        float er  = expf(ar), s, c;
        sincosf(ai, &s, &c);
        float2 z = make_float2(er * c, er * s);   // w = exp(dtA)
        #pragma unroll
        for (int k = 0; k < NPOW; k++) {          // pw[k] = w^(2^k)
            sPow[n][k] = z;
            z = make_float2(z.x * z.x - z.y * z.y, 2.0f * z.x * z.y);
        }
        // D = (exp(dtA) - 1) / A
        float2 w0 = sPow[n][0];
        float Er = w0.x - 1.0f, Ei = w0.y;
        float inv = 1.0f / (ar0 * ar0 + ai0 * ai0);
        float Dr = (Er * ar0 + Ei * ai0) * inv;
        float Di = (Ei * ar0 - Er * ai0) * inv;
        // Ccf = 2 * Cc * D
        float cr = C[2 * g], ci = C[2 * g + 1];
        sCcf[n] = make_float2(2.0f * (cr * Dr - ci * Di),
                              2.0f * (cr * Di + ci * Dr));
    }
    __syncthreads();

    // ---------- Phase 2: fused P from power table ----------
    // sPc[n][jp] = ( Re w^(256jp), Re w^(256jp+128), -Im w^(256jp), -Im w^(256jp+128) )
    #pragma unroll
    for (int r = 0; r < (N2 * NJP) / NTHREADS; r++) {   // 4 iters
        int idx = r * NTHREADS + tid;
        int n   = idx >> 4;         // 0..31
        int jp  = idx & 15;         // j-pair
        int j0  = 2 * jp;
        float2 z0 = make_float2(1.0f, 0.0f);
        if (j0 & 2)  z0 = cmul(z0, sPow[n][8]);
        if (j0 & 4)  z0 = cmul(z0, sPow[n][9]);
        if (j0 & 8)  z0 = cmul(z0, sPow[n][10]);
        if (j0 & 16) z0 = cmul(z0, sPow[n][11]);
        float2 z1 = cmul(z0, sPow[n][7]);       // j0+1
        sPc[n][jp] = make_float4(z0.x, z1.x, -z0.y, -z1.y);
    }

    // ---------- Accumulators: acc[i][jp], lo = j=8*jt+2*jp, hi = +1 ----------
    u64 acc[4][4];
    #pragma unroll
    for (int a = 0; a < 4; a++)
        #pragma unroll
        for (int b = 0; b < 4; b++) acc[a][b] = 0ULL;

    #pragma unroll
    for (int pass = 0; pass < 2; pass++) {
        // ----- Q build: anchors from table, depth-16 recurrence, lane-fast STS -----
        {
            const int nl  = tid & 15;           // 0..15 local row
            const int n   = pass * NP + nl;     // global n
            const int seg = tid >> 4;           // 0..7 -> i = 16*seg..
            float2 z = sCcf[n];
            if (seg & 1) z = cmul(z, sPow[n][4]);
            if (seg & 2) z = cmul(z, sPow[n][5]);
            if (seg & 4) z = cmul(z, sPow[n][6]);
            float2 w = sPow[n][0];
            const int ibase = seg * 16;
            #pragma unroll
            for (int k = 0; k < 16; k++) {
                sQ[nl][ibase + k] = z;
                z = make_float2(z.x * w.x - z.y * w.y,
                                z.x * w.y + z.y * w.x);
            }
        }
        __syncthreads();   // Q (and on pass 0, P) ready

        // ----- Mainloop: double-buffered over 16 n-rows -----
        const float4* pc = &sPc[pass * NP][0] + jt * 4;  // row stride NJP float4

        float2 qb[2][4];
        float4 pb[2][4];
        // prefetch m = 0
        qb[0][0] = sQ[0][lane];
        qb[0][1] = sQ[0][lane + 32];
        qb[0][2] = sQ[0][lane + 64];
        qb[0][3] = sQ[0][lane + 96];
        #pragma unroll
        for (int k = 0; k < 4; k++) pb[0][k] = pc[k];

        #pragma unroll
        for (int m = 0; m < NP; m++) {
            const int cur = m & 1, nxt = cur ^ 1;
            if (m + 1 < NP) {   // prefetch next n
                qb[nxt][0] = sQ[m + 1][lane];
                qb[nxt][1] = sQ[m + 1][lane + 32];
                qb[nxt][2] = sQ[m + 1][lane + 64];
                qb[nxt][3] = sQ[m + 1][lane + 96];
                #pragma unroll
                for (int k = 0; k < 4; k++) pb[nxt][k] = pc[(m + 1) * NJP + k];
            }
            // unpack (scalar packs -> never splits fma2)
            u64 pxv[4], pnyv[4], qr[4], qi[4];
            #pragma unroll
            for (int jp = 0; jp < 4; jp++) {
                pxv[jp]  = pack2(pb[cur][jp].x, pb[cur][jp].y);
                pnyv[jp] = pack2(pb[cur][jp].z, pb[cur][jp].w);
            }
            #pragma unroll
            for (int i = 0; i < 4; i++) {
                qr[i] = pack2(qb[cur][i].x, qb[cur][i].x);
                qi[i] = pack2(qb[cur][i].y, qb[cur][i].y);
            }
            // half-sweep 1: 16 independent fma2 (px * qr)
            #pragma unroll
            for (int i = 0; i < 4; i++)
                #pragma unroll
                for (int jp = 0; jp < 4; jp++)
                    acc[i][jp] = fma2(pxv[jp], qr[i], acc[i][jp]);
            // half-sweep 2: 16 independent fma2 (pny * qi)
            #pragma unroll
            for (int i = 0; i < 4; i++)
                #pragma unroll
                for (int jp = 0; jp < 4; jp++)
                    acc[i][jp] = fma2(pnyv[jp], qi[i], acc[i][jp]);
        }
        __syncthreads();   // done reading sQ before next pass overwrites
    }

    // ---------- Store: coalesced across lanes ----------
    float* outh = out + (size_t)h * (size_t)L + jt * 8 * TT;
    #pragma unroll
    for (int jp = 0; jp < 4; jp++) {
        #pragma unroll
        for (int i = 0; i < 4; i++) {
            float2 v = unpack2(acc[i][jp]);
            outh[(2 * jp + 0) * TT + lane + 32 * i] = v.x;
            outh[(2 * jp + 1) * TT + lane + 32 * i] = v.y;
        }
    }
}

extern "C" void kernel_launch(void* const* d_in, const int* in_sizes, int n_in,
                              void* d_out, int out_size) {
    // inputs: [0]=L (scalar), [1]=log_dt (H), [2]=C (H,N2,2),
    //         [3]=log_A_real (H,N2), [4]=A_imag (H,N2)
    const float* log_dt     = (const float*)d_in[1];
    const float* C          = (const float*)d_in[2];
    const float* log_A_real = (const float*)d_in[3];
    const float* A_imag     = (const float*)d_in[4];
    float* out = (float*)d_out;

    int H = in_sizes[1];          // 1024
    int L = out_size / H;         // 4096  (layout assumes L/128 = 32)

    s4d_vandermonde_kernel<<<H, NTHREADS>>>(log_dt, C, log_A_real, A_imag, out, L);
}